// round 16
// baseline (speedup 1.0000x reference)
#include <cuda_runtime.h>
#include <cuda_bf16.h>
#include <math.h>
#include <stdint.h>

// ---------------- problem constants ----------------
#define NG        50
#define KNB       32
#define NUM_G     64
#define ATOMS     128
#define NTOT      (NUM_G * ATOMS)     // 8192
#define HID       128
#define FIL       128
#define LAYERS    6
#define EDGES     (NTOT * KNB)        // 262144
#define NTILES    (EDGES / 128)       // 2048
#define CUTOFF    10.0f
#define PI_C      3.14159265f

#define INVALID_KEY 0xFFFFFFFFFFFFFFFFULL
typedef unsigned long long ull;

// ---------------- device scratch ----------------
__device__ int   g_idx [EDGES];
__device__ float g_dist[EDGES];
__device__ float g_cval[EDGES];
__device__ float g_h   [NTOT * HID];
__device__ float g_x1  [NTOT * FIL];
__device__ float g_x1q [NTOT * FIL];     // x1 * b2 (next filter layer), precomputed
__device__ float g_agg [NTOT * FIL];

// ldmatrix-layout bf16 tile images
__device__ unsigned char g_rbf_hi[NTILES * 16384];   // per tile: [128 e][64 k], k=50 column = 1.0
__device__ unsigned char g_w1_hi [LAYERS * 16384];   // [128 n][64 k], k=50 row = b1
__device__ unsigned char g_w2_hi [LAYERS * 32768];   // [128 n][128 k], n-permuted
__device__ unsigned char g_l1img [LAYERS * 32768];   // [128 n][128 k]
__device__ unsigned char g_l2img [LAYERS * 32768];   // [128 n][128 k]

// fast silu
__device__ __forceinline__ float silu_f(float v) {
    float e;
    asm("ex2.approx.f32 %0, %1;" : "=f"(e) : "f"(-1.442695041f * v));
    float r;
    asm("rcp.approx.f32 %0, %1;" : "=f"(r) : "f"(1.0f + e));
    return v * r;
}

__device__ __forceinline__ void red_add_v4(float* p, float a, float b, float c, float d) {
    asm volatile("red.global.add.v4.f32 [%0], {%1,%2,%3,%4};"
                 :: "l"(p), "f"(a), "f"(b), "f"(c), "f"(d) : "memory");
}

__device__ __forceinline__ uint32_t smem_u32(const void* p) {
    uint32_t a;
    asm("{ .reg .u64 t; cvta.to.shared.u64 t, %1; cvt.u32.u64 %0, t; }" : "=r"(a) : "l"(p));
    return a;
}

// ---------------- cp.async helpers ----------------
__device__ __forceinline__ void cp_async16(uint32_t saddr, const void* gaddr) {
    asm volatile("cp.async.cg.shared.global [%0], [%1], 16;" :: "r"(saddr), "l"(gaddr));
}
#define CP_COMMIT() asm volatile("cp.async.commit_group;" ::: "memory")
#define CP_WAIT0()  asm volatile("cp.async.wait_group 0;" ::: "memory")

// ---------------- mma.sync / ldmatrix helpers ----------------
__device__ __forceinline__ void ldsm4(uint32_t* r, uint32_t addr) {
    asm volatile("ldmatrix.sync.aligned.m8n8.x4.shared.b16 {%0,%1,%2,%3}, [%4];"
                 : "=r"(r[0]), "=r"(r[1]), "=r"(r[2]), "=r"(r[3]) : "r"(addr));
}
__device__ __forceinline__ void mma16816(float* c, const uint32_t* a, uint32_t b0, uint32_t b1) {
    asm volatile("mma.sync.aligned.m16n8k16.row.col.f32.bf16.bf16.f32 "
                 "{%0,%1,%2,%3}, {%4,%5,%6,%7}, {%8,%9}, {%0,%1,%2,%3};"
                 : "+f"(c[0]), "+f"(c[1]), "+f"(c[2]), "+f"(c[3])
                 : "r"(a[0]), "r"(a[1]), "r"(a[2]), "r"(a[3]), "r"(b0), "r"(b1));
}

// swizzled byte offsets
__device__ __forceinline__ uint32_t off1(int r, int k) {
    return (uint32_t)(r * 128 + (((k >> 3) ^ (r & 7)) << 4) + (k & 7) * 2);
}
__device__ __forceinline__ uint32_t off2(int r, int k) {
    return (uint32_t)(r * 256 + (((k >> 3) ^ (r & 7)) << 4) + (k & 7) * 2);
}
__device__ __forceinline__ int perm_n(int n) {
    const int a = n >> 3, q = (n >> 1) & 3, h = n & 1;
    return ((a >> 1) << 4) + (q << 2) + ((a & 1) << 1) + h;
}

__device__ __forceinline__ uint32_t packbf2(float a, float b) {
    return (uint32_t)__bfloat16_as_ushort(__float2bfloat16(a)) |
           ((uint32_t)__bfloat16_as_ushort(__float2bfloat16(b)) << 16);
}

// ---------------- graph build ----------------
__global__ void build_graph_kernel(const float* __restrict__ pos,
                                   const int* __restrict__ batch)
{
    const int wid  = threadIdx.x >> 5;
    const int lane = threadIdx.x & 31;
    const int i    = blockIdx.x * 4 + wid;
    const int base = (i >> 7) << 7;

    const float px = pos[3*i], py = pos[3*i+1], pz = pos[3*i+2];

    ull key[4];
    #pragma unroll
    for (int c = 0; c < 4; c++) {
        const int j = base + c * 32 + lane;
        const float dx = pos[3*j]   - px;
        const float dy = pos[3*j+1] - py;
        const float dz = pos[3*j+2] - pz;
        const float d2 = dx*dx + dy*dy + dz*dz;
        key[c] = (j != i && d2 < CUTOFF*CUTOFF)
            ? ((((ull)__float_as_uint(d2)) << 32) | (unsigned int)j)
            : INVALID_KEY;
    }

    for (int k = 0; k < KNB; k++) {
        ull m0 = key[0] < key[1] ? key[0] : key[1];
        ull m1 = key[2] < key[3] ? key[2] : key[3];
        ull m  = m0 < m1 ? m0 : m1;
        #pragma unroll
        for (int s = 16; s >= 1; s >>= 1) {
            ull o = __shfl_xor_sync(0xffffffffu, m, s);
            if (o < m) m = o;
        }
        #pragma unroll
        for (int c = 0; c < 4; c++)
            if (key[c] == m) key[c] = INVALID_KEY;
        if (lane == k) {
            const int eo = i * KNB + k;
            if (m != INVALID_KEY) {
                const int   jj = (int)(m & 0xffffffffu);
                const float d  = sqrtf(__uint_as_float((unsigned int)(m >> 32)));
                g_idx[eo]  = jj;
                g_dist[eo] = d;
                const float cv = 0.5f * (cosf(d * (PI_C / CUTOFF)) + 1.0f);
                g_cval[eo] = (d < CUTOFF) ? cv : 0.0f;
            } else {
                g_idx[eo]  = i;
                g_dist[eo] = 1.0f;
                g_cval[eo] = 0.0f;
            }
        }
    }
}

// ---------------- RBF prep: edge-per-thread, windowed Gaussian product form ----------
__global__ void rbf_prep_kernel()
{
    const int e = blockIdx.x * blockDim.x + threadIdx.x;
    if (e >= EDGES) return;
    const float winv = (float)(NG - 1) / CUTOFF;
    const float u = g_dist[e] * winv;
    const int   i = (int)floorf(u);
    const float f = u - (float)i;
    const float F = __expf(-0.5f * f * f);
    const float g = __expf(-f);
    const float h = __expf(f);
    const float T1[14] = {1.0f, 6.0653066e-1f, 1.3533528e-1f, 1.1108997e-2f,
        3.3546263e-4f, 3.7266532e-6f, 1.5229979e-8f, 2.2897348e-11f,
        1.2664166e-14f, 2.5767614e-18f, 1.9287498e-22f, 5.3110924e-27f,
        5.3801861e-32f, 2.0050816e-37f};

    unsigned short row[64];
    #pragma unroll
    for (int k = 0; k < 64; k++) row[k] = 0;
    if (i >= 0 && i < NG)
        row[i] = __bfloat16_as_ushort(__float2bfloat16(F));
    float gp = 1.0f, hp = 1.0f;
    #pragma unroll 1
    for (int m = 1; m <= 13; m++) {
        gp *= g; hp *= h;
        const float t = T1[m] * F;
        const int kd = i - m, ku = i + m;
        if (kd >= 0 && kd < NG)
            row[kd] = __bfloat16_as_ushort(__float2bfloat16(t * gp));
        if (ku >= 0 && ku < NG)
            row[ku] = __bfloat16_as_ushort(__float2bfloat16(t * hp));
    }
    row[NG] = __bfloat16_as_ushort(__float2bfloat16(1.0f));   // bias column

    const int tile = e >> 7, r = e & 127;
    uint4* basep = (uint4*)(g_rbf_hi + (size_t)tile * 16384 + r * 128);
    const uint4* src = (const uint4*)row;
    #pragma unroll
    for (int c = 0; c < 8; c++)
        basep[c ^ (r & 7)] = src[c];
}

// ---------------- fused prep (weights + embed only) ----------------
#define PREP_W1    (LAYERS * 128 * 64)
#define PREP_W2    (LAYERS * 128 * 128)
#define PREP_L1    (LAYERS * 128 * 128)
#define PREP_L2    (LAYERS * 128 * 128)
#define PREP_EMB   (NTOT * HID)
#define PREP_TOTAL (PREP_W1 + PREP_W2 + PREP_L1 + PREP_L2 + PREP_EMB)

__global__ void prep_all_kernel(const float* __restrict__ mw1,
                                const float* __restrict__ mb1,
                                const float* __restrict__ mw2,
                                const float* __restrict__ l1w,
                                const float* __restrict__ l2w,
                                const int* __restrict__ z,
                                const float* __restrict__ emb)
{
    const int id = blockIdx.x * blockDim.x + threadIdx.x;
    if (id < PREP_W1) {
        const int t = id;
        const int l = t >> 13;
        const int n = (t >> 6) & 127;
        const int k = t & 63;
        float val;
        if (k < NG)       val = mw1[l * NG * FIL + k * FIL + n];
        else if (k == NG) val = mb1[l * FIL + n];
        else              val = 0.0f;
        const uint32_t o = (uint32_t)l * 16384u + off1(n, k);
        *(unsigned short*)(g_w1_hi + o) = __bfloat16_as_ushort(__float2bfloat16(val));
    } else if (id < PREP_W1 + PREP_W2) {
        const int t = id - PREP_W1;
        const int l = t >> 14;
        const int n = (t >> 7) & 127;
        const int k = t & 127;
        const float val = mw2[l * FIL * FIL + k * FIL + perm_n(n)];
        const uint32_t o = (uint32_t)l * 32768u + off2(n, k);
        *(unsigned short*)(g_w2_hi + o) = __bfloat16_as_ushort(__float2bfloat16(val));
    } else if (id < PREP_W1 + PREP_W2 + PREP_L1) {
        const int t = id - PREP_W1 - PREP_W2;
        const int l = t >> 14;
        const int n = (t >> 7) & 127;
        const int k = t & 127;
        const float val = l1w[l * HID * FIL + k * FIL + n];
        const uint32_t o = (uint32_t)l * 32768u + off2(n, k);
        *(unsigned short*)(g_l1img + o) = __bfloat16_as_ushort(__float2bfloat16(val));
    } else if (id < PREP_W1 + PREP_W2 + PREP_L1 + PREP_L2) {
        const int t = id - PREP_W1 - PREP_W2 - PREP_L1;
        const int l = t >> 14;
        const int n = (t >> 7) & 127;
        const int k = t & 127;
        const float val = l2w[l * FIL * HID + k * HID + n];
        const uint32_t o = (uint32_t)l * 32768u + off2(n, k);
        *(unsigned short*)(g_l2img + o) = __bfloat16_as_ushort(__float2bfloat16(val));
    } else if (id < PREP_TOTAL) {
        const int t = id - PREP_W1 - PREP_W2 - PREP_L1 - PREP_L2;
        const int n = t >> 7;
        const int c = t & 127;
        g_h[t] = emb[z[n] * HID + c];
    }
}

// ---------------- node linear via mma.sync (512 thr, 64-row tile, single-term) ----------
// weights + bias staged via cp.async, overlapped with activation staging.
#define LIN_A    0
#define LIN_W    16384
#define LIN_B    49152
#define LIN_SMEM_BYTES (49152 + 512)

__global__ void __launch_bounds__(512, 1)
linear_mma_kernel(const float* __restrict__ x,
                  const unsigned char* __restrict__ wimg,
                  const float* __restrict__ b,
                  const float* __restrict__ b2f,
                  float* __restrict__ y,
                  int mode)
{
    extern __shared__ unsigned char base[];
    const uint32_t base32 = smem_u32(base);

    const int tid  = threadIdx.x;
    const int lane = tid & 31;
    const int wid  = tid >> 5;
    const int m0w  = (wid & 3) * 16;
    const int n0w  = (wid >> 2) * 32;
    const int r0   = blockIdx.x * 64;

    // async weight + bias staging (overlaps with activation staging below)
    {
        for (int i = tid; i < 2048; i += 512)
            cp_async16(base32 + LIN_W + i * 16, wimg + i * 16);
        if (tid < 32)
            cp_async16(base32 + LIN_B + tid * 16, (const unsigned char*)b + tid * 16);
        CP_COMMIT();
    }

    {
        const int r  = tid >> 3;
        const int k0 = (tid & 7) * 16;
        const float4* xp = (const float4*)(x + (r0 + r) * 128 + k0);
        float4 v0 = xp[0], v1 = xp[1], v2 = xp[2], v3 = xp[3];
        float vv[16];
        *(float4*)&vv[0]  = v0; *(float4*)&vv[4]  = v1;
        *(float4*)&vv[8]  = v2; *(float4*)&vv[12] = v3;
        #pragma unroll
        for (int g = 0; g < 2; g++) {
            uint4 hi;
            uint32_t* hp = (uint32_t*)&hi;
            #pragma unroll
            for (int j = 0; j < 4; j++)
                hp[j] = packbf2(vv[g*8 + 2*j], vv[g*8 + 2*j + 1]);
            *(uint4*)(base + LIN_A + off2(r, k0 + g * 8)) = hi;
        }
    }
    CP_WAIT0();
    __syncthreads();

    const int lr = lane & 15;
    const int lk = (lane >> 4) * 8;

    float acc[4][4];
    #pragma unroll
    for (int nj = 0; nj < 4; nj++)
        #pragma unroll
        for (int q = 0; q < 4; q++) acc[nj][q] = 0.0f;

    #pragma unroll
    for (int ks = 0; ks < 8; ks++) {
        const int kb = ks * 16 + lk;
        uint32_t Ah[4];
        ldsm4(Ah, base32 + LIN_A + off2(m0w + lr, kb));
        #pragma unroll
        for (int nt = 0; nt < 2; nt++) {
            uint32_t Bh[4];
            ldsm4(Bh, base32 + LIN_W + off2(n0w + nt * 16 + lr, kb));
            #pragma unroll
            for (int h = 0; h < 2; h++)
                mma16816(acc[nt * 2 + h], Ah, Bh[h], Bh[2 + h]);
        }
    }

    {
        float* sb = (float*)(base + LIN_B);
        const int rbase = m0w + (lane >> 2);
        const int cbase = n0w + (lane & 3) * 2;
        #pragma unroll
        for (int nj = 0; nj < 4; nj++) {
            const int col = cbase + nj * 8;
            const float bb0 = sb[col], bb1 = sb[col + 1];
            #pragma unroll
            for (int half = 0; half < 2; half++) {
                const int row = r0 + rbase + half * 8;
                const float v0 = acc[nj][half * 2]     + bb0;
                const float v1 = acc[nj][half * 2 + 1] + bb1;
                float2* yp = (float2*)(y + row * 128 + col);
                if (mode == 0) {
                    float2 v; v.x = v0; v.y = v1;
                    *yp = v;
                    float2 q; q.x = v0 * b2f[col]; q.y = v1 * b2f[col + 1];
                    *(float2*)(g_x1q + row * 128 + col) = q;
                } else {
                    float2 v = *yp;
                    v.x += silu_f(v0);
                    v.y += silu_f(v1);
                    *yp = v;
                }
            }
        }
    }
    if (mode == 0) {
        const int r  = r0 + (tid >> 3);
        const int k0 = (tid & 7) * 16;
        float4 zz; zz.x = zz.y = zz.z = zz.w = 0.0f;
        float4* ap = (float4*)(g_agg + r * 128 + k0);
        ap[0] = zz; ap[1] = zz; ap[2] = zz; ap[3] = zz;
    }
}

// ---------------- fused linear pair (single-term, async weight staging) ----------------
#define FL_A    0
#define FL_W2   16384
#define FL_W1   49152
#define FL_B2   81920
#define FL_B1   82432
#define FL_SMEM_BYTES 82944

__global__ void __launch_bounds__(512, 1)
fused_linear_kernel(const unsigned char* __restrict__ w2img, const float* __restrict__ b2,
                    const unsigned char* __restrict__ w1img, const float* __restrict__ b1,
                    const float* __restrict__ b2next)
{
    extern __shared__ unsigned char base[];
    const uint32_t base32 = smem_u32(base);

    const int tid  = threadIdx.x;
    const int lane = tid & 31;
    const int wid  = tid >> 5;
    const int m0w  = (wid & 3) * 16;
    const int n0w  = (wid >> 2) * 32;
    const int r0   = blockIdx.x * 64;

    // async staging of both weight images + biases
    {
        for (int i = tid; i < 2048; i += 512) {
            cp_async16(base32 + FL_W2 + i * 16, w2img + i * 16);
            cp_async16(base32 + FL_W1 + i * 16, w1img + i * 16);
        }
        if (tid < 32) {
            cp_async16(base32 + FL_B2 + tid * 16, (const unsigned char*)b2 + tid * 16);
            cp_async16(base32 + FL_B1 + tid * 16, (const unsigned char*)b1 + tid * 16);
        }
        CP_COMMIT();
    }

    {
        const int r  = tid >> 3;
        const int k0 = (tid & 7) * 16;
        const float4* xp = (const float4*)(g_agg + (r0 + r) * 128 + k0);
        float4 v0 = xp[0], v1 = xp[1], v2 = xp[2], v3 = xp[3];
        float vv[16];
        *(float4*)&vv[0]  = v0; *(float4*)&vv[4]  = v1;
        *(float4*)&vv[8]  = v2; *(float4*)&vv[12] = v3;
        #pragma unroll
        for (int g = 0; g < 2; g++) {
            uint4 hi;
            uint32_t* hp = (uint32_t*)&hi;
            #pragma unroll
            for (int j = 0; j < 4; j++)
                hp[j] = packbf2(vv[g*8 + 2*j], vv[g*8 + 2*j + 1]);
            *(uint4*)(base + FL_A + off2(r, k0 + g * 8)) = hi;
        }
    }
    CP_WAIT0();
    __syncthreads();

    const int lr = lane & 15;
    const int lk = (lane >> 4) * 8;

    float acc[4][4];
    #pragma unroll
    for (int nj = 0; nj < 4; nj++)
        #pragma unroll
        for (int q = 0; q < 4; q++) acc[nj][q] = 0.0f;

    // GEMM A: agg @ W2
    #pragma unroll
    for (int ks = 0; ks < 8; ks++) {
        const int kb = ks * 16 + lk;
        uint32_t Ah[4];
        ldsm4(Ah, base32 + FL_A + off2(m0w + lr, kb));
        #pragma unroll
        for (int nt = 0; nt < 2; nt++) {
            uint32_t Bh[4];
            ldsm4(Bh, base32 + FL_W2 + off2(n0w + nt * 16 + lr, kb));
            #pragma unroll
            for (int h = 0; h < 2; h++)
                mma16816(acc[nt * 2 + h], Ah, Bh[h], Bh[2 + h]);
        }
    }
    __syncthreads();

    // epilogue A: h_new = h_old + silu(acc + b2); restage bf16
    {
        float* sb2 = (float*)(base + FL_B2);
        const int rbase = m0w + (lane >> 2);
        const int cbase = n0w + (lane & 3) * 2;
        #pragma unroll
        for (int nj = 0; nj < 4; nj++) {
            const int col = cbase + nj * 8;
            const float bb0 = sb2[col], bb1 = sb2[col + 1];
            #pragma unroll
            for (int half = 0; half < 2; half++) {
                const int rloc = rbase + half * 8;
                const int row  = r0 + rloc;
                float2* hptr = (float2*)(g_h + row * 128 + col);
                float2 hv = *hptr;
                const float v0 = hv.x + silu_f(acc[nj][half * 2]     + bb0);
                const float v1 = hv.y + silu_f(acc[nj][half * 2 + 1] + bb1);
                float2 nv; nv.x = v0; nv.y = v1;
                *hptr = nv;
                *(uint32_t*)(base + FL_A + off2(rloc, col)) = packbf2(v0, v1);
            }
        }
    }
    __syncthreads();

    #pragma unroll
    for (int nj = 0; nj < 4; nj++)
        #pragma unroll
        for (int q = 0; q < 4; q++) acc[nj][q] = 0.0f;

    // GEMM B: h_new @ W1
    #pragma unroll
    for (int ks = 0; ks < 8; ks++) {
        const int kb = ks * 16 + lk;
        uint32_t Ah[4];
        ldsm4(Ah, base32 + FL_A + off2(m0w + lr, kb));
        #pragma unroll
        for (int nt = 0; nt < 2; nt++) {
            uint32_t Bh[4];
            ldsm4(Bh, base32 + FL_W1 + off2(n0w + nt * 16 + lr, kb));
            #pragma unroll
            for (int h = 0; h < 2; h++)
                mma16816(acc[nt * 2 + h], Ah, Bh[h], Bh[2 + h]);
        }
    }

    // epilogue B: x1 = acc + b1; x1q = x1*b2next; zero agg rows
    {
        float* sb1 = (float*)(base + FL_B1);
        const int rbase = m0w + (lane >> 2);
        const int cbase = n0w + (lane & 3) * 2;
        #pragma unroll
        for (int nj = 0; nj < 4; nj++) {
            const int col = cbase + nj * 8;
            const float bb0 = sb1[col], bb1 = sb1[col + 1];
            const float q0 = b2next[col], q1 = b2next[col + 1];
            #pragma unroll
            for (int half = 0; half < 2; half++) {
                const int row = r0 + rbase + half * 8;
                const float v0 = acc[nj][half * 2]     + bb0;
                const float v1 = acc[nj][half * 2 + 1] + bb1;
                float2 v; v.x = v0; v.y = v1;
                *(float2*)(g_x1 + row * 128 + col) = v;
                float2 q; q.x = v0 * q0; q.y = v1 * q1;
                *(float2*)(g_x1q + row * 128 + col) = q;
            }
        }
    }
    {
        const int r  = r0 + (tid >> 3);
        const int k0 = (tid & 7) * 16;
        float4 zz; zz.x = zz.y = zz.z = zz.w = 0.0f;
        float4* ap = (float4*)(g_agg + r * 128 + k0);
        ap[0] = zz; ap[1] = zz; ap[2] = zz; ap[3] = zz;
    }
}

// ---------------- tensor-core filter kernel, 512 threads ----------------
#define SO_A1   0                 // 2 x 16384 (parity)
#define SO_A2   32768             // 32768
#define SO_B1   65536             // 16384
#define SO_B2   81920             // 32768
#define SO_AUX  114688            // 2 x 5120 (parity)
#define AUXB_X1P 0
#define AUXB_X1Q 2048
#define AUXB_CV  4096
#define AUXB_DST 4608
#define FILT_SMEM_BYTES (SO_AUX + 10240)

__device__ __forceinline__ void filt_prefetch(uint32_t base32, int tile, int par, int tid)
{
    if (tile >= NTILES) return;
    const size_t tb = (size_t)tile * 16384;
    for (int i = tid; i < 1024; i += 512)
        cp_async16(base32 + SO_A1 + par * 16384 + i * 16, g_rbf_hi + tb + i * 16);
    const uint32_t auxb = base32 + SO_AUX + par * 5120;
    if (tid < 128) {
        cp_async16(auxb + AUXB_X1P + tid * 16,
                   (const unsigned char*)g_x1  + (size_t)tile * 2048 + tid * 16);
        cp_async16(auxb + AUXB_X1Q + tid * 16,
                   (const unsigned char*)g_x1q + (size_t)tile * 2048 + tid * 16);
    } else if (tid < 160) {
        const int j = tid - 128;
        cp_async16(auxb + AUXB_CV + j * 16,
                   (const unsigned char*)g_cval + (size_t)tile * 512 + j * 16);
    } else if (tid < 192) {
        const int j = tid - 160;
        cp_async16(auxb + AUXB_DST + j * 16,
                   (const unsigned char*)g_idx + (size_t)tile * 512 + j * 16);
    }
}

__global__ void __launch_bounds__(512, 1)
filter_mma_kernel(const unsigned char* __restrict__ w1hi,
                  const unsigned char* __restrict__ w2hi)
{
    extern __shared__ unsigned char base[];
    const uint32_t base32 = smem_u32(base);

    const int tid  = threadIdx.x;
    const int lane = tid & 31;
    const int wid  = tid >> 5;
    const int wm   = wid & 3;          // warp m-tile: 32 edges
    const int wn   = wid >> 2;         // warp n-tile: 32 channels
    const int m0w  = wm * 32;
    const int n0w  = wn * 32;

    // resident weight copies
    {
        const uint4* s1h = (const uint4*)w1hi;
        const uint4* s2h = (const uint4*)w2hi;
        uint4* d1h = (uint4*)(base + SO_B1);
        uint4* d2h = (uint4*)(base + SO_B2);
        for (int i = tid; i < 1024; i += 512) d1h[i] = s1h[i];
        for (int i = tid; i < 2048; i += 512) d2h[i] = s2h[i];
    }

    filt_prefetch(base32, blockIdx.x, 0, tid);
    CP_COMMIT();

    const int lr = lane & 15;
    const int lk = (lane >> 4) * 8;

    __syncthreads();    // weights visible

    // B1 fragments register-resident (tile-invariant)
    uint32_t B1r[4][2][4];
    #pragma unroll
    for (int ks = 0; ks < 4; ks++) {
        const int kb = ks * 16 + lk;
        #pragma unroll
        for (int nt = 0; nt < 2; nt++)
            ldsm4(B1r[ks][nt], base32 + SO_B1 + off1(n0w + nt * 16 + lr, kb));
    }

    int par = 0;
    for (int tile = blockIdx.x; tile < NTILES; tile += gridDim.x, par ^= 1) {
        unsigned char* aux = base + SO_AUX + par * 5120;
        float* sx1p = (float*)(aux + AUXB_X1P);
        float* sx1q = (float*)(aux + AUXB_X1Q);
        float* scv  = (float*)(aux + AUXB_CV);
        int*   sdst = (int*)  (aux + AUXB_DST);

        CP_WAIT0();
        __syncthreads();

        filt_prefetch(base32, tile + gridDim.x, par ^ 1, tid);
        CP_COMMIT();

        float acc[2][4][4];
        #pragma unroll
        for (int mi = 0; mi < 2; mi++)
            #pragma unroll
            for (int nj = 0; nj < 4; nj++)
                #pragma unroll
                for (int q = 0; q < 4; q++) acc[mi][nj][q] = 0.0f;

        // ---- GEMM1: K=64 (bias folded), B from registers ----
        const uint32_t a1b = base32 + SO_A1 + par * 16384;
        #pragma unroll
        for (int ks = 0; ks < 4; ks++) {
            const int kb = ks * 16 + lk;
            uint32_t Ah[2][4];
            #pragma unroll
            for (int mi = 0; mi < 2; mi++)
                ldsm4(Ah[mi], a1b + off1(m0w + mi * 16 + lr, kb));
            #pragma unroll
            for (int nt = 0; nt < 2; nt++)
                #pragma unroll
                for (int h = 0; h < 2; h++) {
                    const int nj = nt * 2 + h;
                    #pragma unroll
                    for (int mi = 0; mi < 2; mi++)
                        mma16816(acc[mi][nj], Ah[mi], B1r[ks][nt][h], B1r[ks][nt][2 + h]);
                }
        }

        // ---- epilogue1: silu -> bf16 -> A2 ----
        {
            unsigned char* a2h = base + SO_A2;
            const int rbase = m0w + (lane >> 2);
            const int cbase = n0w + (lane & 3) * 2;
            #pragma unroll
            for (int mi = 0; mi < 2; mi++)
                #pragma unroll
                for (int nj = 0; nj < 4; nj++) {
                    const int col = cbase + nj * 8;
                    #pragma unroll
                    for (int half = 0; half < 2; half++) {
                        const int row = rbase + mi * 16 + half * 8;
                        const float s0 = silu_f(acc[mi][nj][half * 2]);
                        const float s1 = silu_f(acc[mi][nj][half * 2 + 1]);
                        *(uint32_t*)(a2h + off2(row, col)) = packbf2(s0, s1);
                    }
                }
        }
        asm volatile("bar.sync %0, %1;" :: "r"(1 + wm), "r"(128) : "memory");

        #pragma unroll
        for (int mi = 0; mi < 2; mi++)
            #pragma unroll
            for (int nj = 0; nj < 4; nj++)
                #pragma unroll
                for (int q = 0; q < 4; q++) acc[mi][nj][q] = 0.0f;

        // ---- GEMM2: K=128 ----
        #pragma unroll
        for (int ks = 0; ks < 8; ks++) {
            const int kb = ks * 16 + lk;
            uint32_t Ah[2][4];
            #pragma unroll
            for (int mi = 0; mi < 2; mi++)
                ldsm4(Ah[mi], base32 + SO_A2 + off2(m0w + mi * 16 + lr, kb));
            #pragma unroll
            for (int nt = 0; nt < 2; nt++) {
                uint32_t Bh[4];
                ldsm4(Bh, base32 + SO_B2 + off2(n0w + nt * 16 + lr, kb));
                #pragma unroll
                for (int h = 0; h < 2; h++) {
                    const int nj = nt * 2 + h;
                    #pragma unroll
                    for (int mi = 0; mi < 2; mi++)
                        mma16816(acc[mi][nj], Ah[mi], Bh[h], Bh[2 + h]);
                }
            }
        }

        // ---- epilogue2: permuted channels -> red.v4 ----
        {
            const int q4 = (lane & 3) << 2;
            const int rbase = m0w + (lane >> 2);
            const int j4 = m0w >> 5;
            const float* pv = &sx1p[j4 * 128];
            const float* qv = &sx1q[j4 * 128];
            #pragma unroll
            for (int mi = 0; mi < 2; mi++)
                #pragma unroll
                for (int half = 0; half < 2; half++) {
                    const int row = rbase + mi * 16 + half * 8;
                    const float cv = scv[row];
                    const int   dst = sdst[row];
                    float* aggp = &g_agg[dst * 128];
                    #pragma unroll
                    for (int pj = 0; pj < 2; pj++) {
                        const int pb = n0w + (pj << 4) + q4;
                        const float4 pvv = *(const float4*)&pv[pb];
                        const float4 qvv = *(const float4*)&qv[pb];
                        const float m0 = cv * fmaf(acc[mi][2*pj    ][half * 2],     pvv.x, qvv.x);
                        const float m1 = cv * fmaf(acc[mi][2*pj    ][half * 2 + 1], pvv.y, qvv.y);
                        const float m2 = cv * fmaf(acc[mi][2*pj + 1][half * 2],     pvv.z, qvv.z);
                        const float m3 = cv * fmaf(acc[mi][2*pj + 1][half * 2 + 1], pvv.w, qvv.w);
                        red_add_v4(aggp + pb, m0, m1, m2, m3);
                    }
                }
        }
    }
}

// ---------------- output head + per-graph sum ----------------
#define OUT_SMEM_FLOATS (128*128 + 128*65)

__global__ void out_kernel(const float* __restrict__ ow1, const float* __restrict__ ob1,
                           const float* __restrict__ ow2, const float* __restrict__ ob2,
                           float* __restrict__ out)
{
    extern __shared__ float sm[];
    float* sh = sm;
    float* st = sh + 128*128;
    __shared__ float rsum[256];

    const int g    = blockIdx.x;
    const int tid  = threadIdx.x;
    const int base = g * ATOMS;

    for (int idx = tid; idx < 128 * 128; idx += 256)
        sh[idx] = g_h[base * 128 + idx];
    __syncthreads();

    const int d   = tid & 63;
    const int grp = tid >> 6;
    float acc[32];
    #pragma unroll
    for (int e = 0; e < 32; e++) acc[e] = 0.0f;
    const float* hh = sh + grp * 32 * 128;
    #pragma unroll 2
    for (int k = 0; k < 128; k++) {
        const float w = ow1[k * 64 + d];
        #pragma unroll
        for (int e = 0; e < 32; e++) acc[e] += hh[e * 128 + k] * w;
    }
    const float bb = ob1[d];
    #pragma unroll
    for (int e = 0; e < 32; e++) {
        const float v = acc[e] + bb;
        st[(grp * 32 + e) * 65 + d] = silu_f(v);
    }
    __syncthreads();

    float o = 0.0f;
    if (tid < 128) {
        float s = ob2[0];
        #pragma unroll 4
        for (int dd = 0; dd < 64; dd++) s += st[tid * 65 + dd] * ow2[dd];
        o = s;
    }
    rsum[tid] = o;
    __syncthreads();
    for (int s = 128; s >= 1; s >>= 1) {
        if (tid < s) rsum[tid] += rsum[tid + s];
        __syncthreads();
    }
    if (tid == 0) out[g] = rsum[0];
}

// ---------------- launch ----------------
extern "C" void kernel_launch(void* const* d_in, const int* in_sizes, int n_in,
                              void* d_out, int out_size)
{
    const float* pos   = (const float*)d_in[0];
    const int*   z     = (const int*)  d_in[1];
    const int*   batch = (const int*)  d_in[2];
    const float* emb   = (const float*)d_in[3];
    const float* mw1   = (const float*)d_in[4];
    const float* mb1   = (const float*)d_in[5];
    const float* mw2   = (const float*)d_in[6];
    const float* mb2   = (const float*)d_in[7];
    const float* l1w   = (const float*)d_in[8];
    const float* l1b   = (const float*)d_in[9];
    const float* l2w   = (const float*)d_in[10];
    const float* l2b   = (const float*)d_in[11];
    const float* ow1   = (const float*)d_in[12];
    const float* ob1   = (const float*)d_in[13];
    const float* ow2   = (const float*)d_in[14];
    const float* ob2   = (const float*)d_in[15];
    float* out = (float*)d_out;

    float *hp, *x1p, *aggp;
    cudaGetSymbolAddress((void**)&hp,   g_h);
    cudaGetSymbolAddress((void**)&x1p,  g_x1);
    cudaGetSymbolAddress((void**)&aggp, g_agg);
    unsigned char *w1h, *w2h, *l1i, *l2i;
    cudaGetSymbolAddress((void**)&w1h, g_w1_hi);
    cudaGetSymbolAddress((void**)&w2h, g_w2_hi);
    cudaGetSymbolAddress((void**)&l1i, g_l1img);
    cudaGetSymbolAddress((void**)&l2i, g_l2img);

    cudaFuncSetAttribute(filter_mma_kernel, cudaFuncAttributeMaxDynamicSharedMemorySize,
                         FILT_SMEM_BYTES);
    cudaFuncSetAttribute(linear_mma_kernel, cudaFuncAttributeMaxDynamicSharedMemorySize,
                         LIN_SMEM_BYTES);
    cudaFuncSetAttribute(fused_linear_kernel, cudaFuncAttributeMaxDynamicSharedMemorySize,
                         FL_SMEM_BYTES);
    cudaFuncSetAttribute(out_kernel, cudaFuncAttributeMaxDynamicSharedMemorySize,
                         OUT_SMEM_FLOATS * (int)sizeof(float));

    build_graph_kernel<<<NTOT / 4, 128>>>(pos, batch);
    rbf_prep_kernel<<<EDGES / 256, 256>>>();
    prep_all_kernel<<<(PREP_TOTAL + 255) / 256, 256>>>(mw1, mb1, mw2, l1w, l2w, z, emb);

    linear_mma_kernel<<<NTOT / 64, 512, LIN_SMEM_BYTES>>>(
        hp, l1i, l1b, mb2, x1p, 0);

    for (int l = 0; l < LAYERS; l++) {
        filter_mma_kernel<<<148, 512, FILT_SMEM_BYTES>>>(
            w1h + l * 16384, w2h + l * 32768);
        if (l < LAYERS - 1) {
            fused_linear_kernel<<<NTOT / 64, 512, FL_SMEM_BYTES>>>(
                l2i + l * 32768, l2b + l * HID,
                l1i + (l + 1) * 32768, l1b + (l + 1) * FIL,
                mb2 + (l + 1) * FIL);
        } else {
            linear_mma_kernel<<<NTOT / 64, 512, LIN_SMEM_BYTES>>>(
                aggp, l2i + l * 32768, l2b + l * HID, mb2, hp, 1);
        }
    }

    out_kernel<<<NUM_G, 256, OUT_SMEM_FLOATS * sizeof(float)>>>(ow1, ob1, ow2, ob2, out);
}

// round 17
// speedup vs baseline: 1.3660x; 1.3660x over previous
#include <cuda_runtime.h>
#include <cuda_bf16.h>
#include <math.h>
#include <stdint.h>

// ---------------- problem constants ----------------
#define NG        50
#define KNB       32
#define NUM_G     64
#define ATOMS     128
#define NTOT      (NUM_G * ATOMS)     // 8192
#define HID       128
#define FIL       128
#define LAYERS    6
#define EDGES     (NTOT * KNB)        // 262144
#define NTILES    (EDGES / 128)       // 2048
#define CUTOFF    10.0f
#define PI_C      3.14159265f

#define INVALID_KEY 0xFFFFFFFFFFFFFFFFULL
typedef unsigned long long ull;

// ---------------- device scratch ----------------
__device__ int   g_idx [EDGES];
__device__ float g_dist[EDGES];
__device__ float g_cval[EDGES];
__device__ float g_h   [NTOT * HID];
__device__ float g_x1  [NTOT * FIL];
__device__ float g_x1q [NTOT * FIL];     // x1 * b2 (next filter layer), precomputed
__device__ float g_agg [NTOT * FIL];

// ldmatrix-layout bf16 tile images
__device__ unsigned char g_rbf_hi[NTILES * 16384];   // per tile: [128 e][64 k], k=50 column = 1.0
__device__ unsigned char g_w1_hi [LAYERS * 16384];   // [128 n][64 k], k=50 row = b1
__device__ unsigned char g_w2_hi [LAYERS * 32768];   // [128 n][128 k], n-permuted
__device__ unsigned char g_l1img [LAYERS * 32768];   // [128 n][128 k]
__device__ unsigned char g_l2img [LAYERS * 32768];   // [128 n][128 k]
__device__ unsigned char g_o1img [16384];            // [64 n][128 k] output head W1

// fast silu
__device__ __forceinline__ float silu_f(float v) {
    float e;
    asm("ex2.approx.f32 %0, %1;" : "=f"(e) : "f"(-1.442695041f * v));
    float r;
    asm("rcp.approx.f32 %0, %1;" : "=f"(r) : "f"(1.0f + e));
    return v * r;
}

__device__ __forceinline__ void red_add_v4(float* p, float a, float b, float c, float d) {
    asm volatile("red.global.add.v4.f32 [%0], {%1,%2,%3,%4};"
                 :: "l"(p), "f"(a), "f"(b), "f"(c), "f"(d) : "memory");
}

__device__ __forceinline__ uint32_t smem_u32(const void* p) {
    uint32_t a;
    asm("{ .reg .u64 t; cvta.to.shared.u64 t, %1; cvt.u32.u64 %0, t; }" : "=r"(a) : "l"(p));
    return a;
}

// ---------------- cp.async helpers ----------------
__device__ __forceinline__ void cp_async16(uint32_t saddr, const void* gaddr) {
    asm volatile("cp.async.cg.shared.global [%0], [%1], 16;" :: "r"(saddr), "l"(gaddr));
}
#define CP_COMMIT() asm volatile("cp.async.commit_group;" ::: "memory")
#define CP_WAIT0()  asm volatile("cp.async.wait_group 0;" ::: "memory")

// ---------------- mma.sync / ldmatrix helpers ----------------
__device__ __forceinline__ void ldsm4(uint32_t* r, uint32_t addr) {
    asm volatile("ldmatrix.sync.aligned.m8n8.x4.shared.b16 {%0,%1,%2,%3}, [%4];"
                 : "=r"(r[0]), "=r"(r[1]), "=r"(r[2]), "=r"(r[3]) : "r"(addr));
}
__device__ __forceinline__ void mma16816(float* c, const uint32_t* a, uint32_t b0, uint32_t b1) {
    asm volatile("mma.sync.aligned.m16n8k16.row.col.f32.bf16.bf16.f32 "
                 "{%0,%1,%2,%3}, {%4,%5,%6,%7}, {%8,%9}, {%0,%1,%2,%3};"
                 : "+f"(c[0]), "+f"(c[1]), "+f"(c[2]), "+f"(c[3])
                 : "r"(a[0]), "r"(a[1]), "r"(a[2]), "r"(a[3]), "r"(b0), "r"(b1));
}

// swizzled byte offsets
__device__ __forceinline__ uint32_t off1(int r, int k) {
    return (uint32_t)(r * 128 + (((k >> 3) ^ (r & 7)) << 4) + (k & 7) * 2);
}
__device__ __forceinline__ uint32_t off2(int r, int k) {
    return (uint32_t)(r * 256 + (((k >> 3) ^ (r & 7)) << 4) + (k & 7) * 2);
}
__device__ __forceinline__ int perm_n(int n) {
    const int a = n >> 3, q = (n >> 1) & 3, h = n & 1;
    return ((a >> 1) << 4) + (q << 2) + ((a & 1) << 1) + h;
}

__device__ __forceinline__ uint32_t packbf2(float a, float b) {
    return (uint32_t)__bfloat16_as_ushort(__float2bfloat16(a)) |
           ((uint32_t)__bfloat16_as_ushort(__float2bfloat16(b)) << 16);
}

// ---------------- graph build ----------------
__global__ void build_graph_kernel(const float* __restrict__ pos,
                                   const int* __restrict__ batch)
{
    const int wid  = threadIdx.x >> 5;
    const int lane = threadIdx.x & 31;
    const int i    = blockIdx.x * 4 + wid;
    const int base = (i >> 7) << 7;

    const float px = pos[3*i], py = pos[3*i+1], pz = pos[3*i+2];

    ull key[4];
    #pragma unroll
    for (int c = 0; c < 4; c++) {
        const int j = base + c * 32 + lane;
        const float dx = pos[3*j]   - px;
        const float dy = pos[3*j+1] - py;
        const float dz = pos[3*j+2] - pz;
        const float d2 = dx*dx + dy*dy + dz*dz;
        key[c] = (j != i && d2 < CUTOFF*CUTOFF)
            ? ((((ull)__float_as_uint(d2)) << 32) | (unsigned int)j)
            : INVALID_KEY;
    }

    for (int k = 0; k < KNB; k++) {
        ull m0 = key[0] < key[1] ? key[0] : key[1];
        ull m1 = key[2] < key[3] ? key[2] : key[3];
        ull m  = m0 < m1 ? m0 : m1;
        #pragma unroll
        for (int s = 16; s >= 1; s >>= 1) {
            ull o = __shfl_xor_sync(0xffffffffu, m, s);
            if (o < m) m = o;
        }
        #pragma unroll
        for (int c = 0; c < 4; c++)
            if (key[c] == m) key[c] = INVALID_KEY;
        if (lane == k) {
            const int eo = i * KNB + k;
            if (m != INVALID_KEY) {
                const int   jj = (int)(m & 0xffffffffu);
                const float d  = sqrtf(__uint_as_float((unsigned int)(m >> 32)));
                g_idx[eo]  = jj;
                g_dist[eo] = d;
                const float cv = 0.5f * (cosf(d * (PI_C / CUTOFF)) + 1.0f);
                g_cval[eo] = (d < CUTOFF) ? cv : 0.0f;
            } else {
                g_idx[eo]  = i;
                g_dist[eo] = 1.0f;
                g_cval[eo] = 0.0f;
            }
        }
    }
}

// ---------------- RBF prep: edge-per-thread, windowed Gaussian product form ----------
__global__ void rbf_prep_kernel()
{
    const int e = blockIdx.x * blockDim.x + threadIdx.x;
    if (e >= EDGES) return;
    const float winv = (float)(NG - 1) / CUTOFF;
    const float u = g_dist[e] * winv;
    const int   i = (int)floorf(u);
    const float f = u - (float)i;
    const float F = __expf(-0.5f * f * f);
    const float g = __expf(-f);
    const float h = __expf(f);
    const float T1[14] = {1.0f, 6.0653066e-1f, 1.3533528e-1f, 1.1108997e-2f,
        3.3546263e-4f, 3.7266532e-6f, 1.5229979e-8f, 2.2897348e-11f,
        1.2664166e-14f, 2.5767614e-18f, 1.9287498e-22f, 5.3110924e-27f,
        5.3801861e-32f, 2.0050816e-37f};

    unsigned short row[64];
    #pragma unroll
    for (int k = 0; k < 64; k++) row[k] = 0;
    if (i >= 0 && i < NG)
        row[i] = __bfloat16_as_ushort(__float2bfloat16(F));
    float gp = 1.0f, hp = 1.0f;
    #pragma unroll 1
    for (int m = 1; m <= 13; m++) {
        gp *= g; hp *= h;
        const float t = T1[m] * F;
        const int kd = i - m, ku = i + m;
        if (kd >= 0 && kd < NG)
            row[kd] = __bfloat16_as_ushort(__float2bfloat16(t * gp));
        if (ku >= 0 && ku < NG)
            row[ku] = __bfloat16_as_ushort(__float2bfloat16(t * hp));
    }
    row[NG] = __bfloat16_as_ushort(__float2bfloat16(1.0f));   // bias column

    const int tile = e >> 7, r = e & 127;
    uint4* basep = (uint4*)(g_rbf_hi + (size_t)tile * 16384 + r * 128);
    const uint4* src = (const uint4*)row;
    #pragma unroll
    for (int c = 0; c < 8; c++)
        basep[c ^ (r & 7)] = src[c];
}

// ---------------- fused prep (weights + embed) ----------------
#define PREP_W1    (LAYERS * 128 * 64)
#define PREP_W2    (LAYERS * 128 * 128)
#define PREP_L1    (LAYERS * 128 * 128)
#define PREP_L2    (LAYERS * 128 * 128)
#define PREP_O1    (64 * 128)
#define PREP_EMB   (NTOT * HID)
#define PREP_TOTAL (PREP_W1 + PREP_W2 + PREP_L1 + PREP_L2 + PREP_O1 + PREP_EMB)

__global__ void prep_all_kernel(const float* __restrict__ mw1,
                                const float* __restrict__ mb1,
                                const float* __restrict__ mw2,
                                const float* __restrict__ l1w,
                                const float* __restrict__ l2w,
                                const float* __restrict__ ow1,
                                const int* __restrict__ z,
                                const float* __restrict__ emb)
{
    const int id = blockIdx.x * blockDim.x + threadIdx.x;
    if (id < PREP_W1) {
        const int t = id;
        const int l = t >> 13;
        const int n = (t >> 6) & 127;
        const int k = t & 63;
        float val;
        if (k < NG)       val = mw1[l * NG * FIL + k * FIL + n];
        else if (k == NG) val = mb1[l * FIL + n];
        else              val = 0.0f;
        const uint32_t o = (uint32_t)l * 16384u + off1(n, k);
        *(unsigned short*)(g_w1_hi + o) = __bfloat16_as_ushort(__float2bfloat16(val));
    } else if (id < PREP_W1 + PREP_W2) {
        const int t = id - PREP_W1;
        const int l = t >> 14;
        const int n = (t >> 7) & 127;
        const int k = t & 127;
        const float val = mw2[l * FIL * FIL + k * FIL + perm_n(n)];
        const uint32_t o = (uint32_t)l * 32768u + off2(n, k);
        *(unsigned short*)(g_w2_hi + o) = __bfloat16_as_ushort(__float2bfloat16(val));
    } else if (id < PREP_W1 + PREP_W2 + PREP_L1) {
        const int t = id - PREP_W1 - PREP_W2;
        const int l = t >> 14;
        const int n = (t >> 7) & 127;
        const int k = t & 127;
        const float val = l1w[l * HID * FIL + k * FIL + n];
        const uint32_t o = (uint32_t)l * 32768u + off2(n, k);
        *(unsigned short*)(g_l1img + o) = __bfloat16_as_ushort(__float2bfloat16(val));
    } else if (id < PREP_W1 + PREP_W2 + PREP_L1 + PREP_L2) {
        const int t = id - PREP_W1 - PREP_W2 - PREP_L1;
        const int l = t >> 14;
        const int n = (t >> 7) & 127;
        const int k = t & 127;
        const float val = l2w[l * FIL * HID + k * HID + n];
        const uint32_t o = (uint32_t)l * 32768u + off2(n, k);
        *(unsigned short*)(g_l2img + o) = __bfloat16_as_ushort(__float2bfloat16(val));
    } else if (id < PREP_W1 + PREP_W2 + PREP_L1 + PREP_L2 + PREP_O1) {
        const int t = id - PREP_W1 - PREP_W2 - PREP_L1 - PREP_L2;
        const int n = t >> 7;          // 0..63
        const int k = t & 127;
        const float val = ow1[k * 64 + n];
        *(unsigned short*)(g_o1img + off2(n, k)) = __bfloat16_as_ushort(__float2bfloat16(val));
    } else if (id < PREP_TOTAL) {
        const int t = id - PREP_W1 - PREP_W2 - PREP_L1 - PREP_L2 - PREP_O1;
        const int n = t >> 7;
        const int c = t & 127;
        g_h[t] = emb[z[n] * HID + c];
    }
}

// ---------------- node linear via mma.sync (512 thr, 64-row tile, single-term) ----------
#define LIN_A    0
#define LIN_W    16384
#define LIN_B    49152
#define LIN_SMEM_BYTES (49152 + 512)

__global__ void __launch_bounds__(512, 1)
linear_mma_kernel(const float* __restrict__ x,
                  const unsigned char* __restrict__ wimg,
                  const float* __restrict__ b,
                  const float* __restrict__ b2f,
                  float* __restrict__ y,
                  int mode)
{
    extern __shared__ unsigned char base[];
    const uint32_t base32 = smem_u32(base);

    const int tid  = threadIdx.x;
    const int lane = tid & 31;
    const int wid  = tid >> 5;
    const int m0w  = (wid & 3) * 16;
    const int n0w  = (wid >> 2) * 32;
    const int r0   = blockIdx.x * 64;

    {
        const uint4* sw = (const uint4*)wimg;
        uint4* dw = (uint4*)(base + LIN_W);
        for (int i = tid; i < 2048; i += 512) dw[i] = sw[i];
        float* sb = (float*)(base + LIN_B);
        if (tid < 128) sb[tid] = b[tid];
    }

    {
        const int r  = tid >> 3;
        const int k0 = (tid & 7) * 16;
        const float4* xp = (const float4*)(x + (r0 + r) * 128 + k0);
        float4 v0 = xp[0], v1 = xp[1], v2 = xp[2], v3 = xp[3];
        float vv[16];
        *(float4*)&vv[0]  = v0; *(float4*)&vv[4]  = v1;
        *(float4*)&vv[8]  = v2; *(float4*)&vv[12] = v3;
        #pragma unroll
        for (int g = 0; g < 2; g++) {
            uint4 hi;
            uint32_t* hp = (uint32_t*)&hi;
            #pragma unroll
            for (int j = 0; j < 4; j++)
                hp[j] = packbf2(vv[g*8 + 2*j], vv[g*8 + 2*j + 1]);
            *(uint4*)(base + LIN_A + off2(r, k0 + g * 8)) = hi;
        }
    }
    __syncthreads();

    const int lr = lane & 15;
    const int lk = (lane >> 4) * 8;

    float acc[4][4];
    #pragma unroll
    for (int nj = 0; nj < 4; nj++)
        #pragma unroll
        for (int q = 0; q < 4; q++) acc[nj][q] = 0.0f;

    #pragma unroll
    for (int ks = 0; ks < 8; ks++) {
        const int kb = ks * 16 + lk;
        uint32_t Ah[4];
        ldsm4(Ah, base32 + LIN_A + off2(m0w + lr, kb));
        #pragma unroll
        for (int nt = 0; nt < 2; nt++) {
            uint32_t Bh[4];
            ldsm4(Bh, base32 + LIN_W + off2(n0w + nt * 16 + lr, kb));
            #pragma unroll
            for (int h = 0; h < 2; h++)
                mma16816(acc[nt * 2 + h], Ah, Bh[h], Bh[2 + h]);
        }
    }

    {
        float* sb = (float*)(base + LIN_B);
        const int rbase = m0w + (lane >> 2);
        const int cbase = n0w + (lane & 3) * 2;
        #pragma unroll
        for (int nj = 0; nj < 4; nj++) {
            const int col = cbase + nj * 8;
            const float bb0 = sb[col], bb1 = sb[col + 1];
            #pragma unroll
            for (int half = 0; half < 2; half++) {
                const int row = r0 + rbase + half * 8;
                const float v0 = acc[nj][half * 2]     + bb0;
                const float v1 = acc[nj][half * 2 + 1] + bb1;
                float2* yp = (float2*)(y + row * 128 + col);
                if (mode == 0) {
                    float2 v; v.x = v0; v.y = v1;
                    *yp = v;
                    float2 q; q.x = v0 * b2f[col]; q.y = v1 * b2f[col + 1];
                    *(float2*)(g_x1q + row * 128 + col) = q;
                } else {
                    float2 v = *yp;
                    v.x += silu_f(v0);
                    v.y += silu_f(v1);
                    *yp = v;
                }
            }
        }
    }
    if (mode == 0) {
        const int r  = r0 + (tid >> 3);
        const int k0 = (tid & 7) * 16;
        float4 zz; zz.x = zz.y = zz.z = zz.w = 0.0f;
        float4* ap = (float4*)(g_agg + r * 128 + k0);
        ap[0] = zz; ap[1] = zz; ap[2] = zz; ap[3] = zz;
    }
}

// ---------------- fused linear pair (single-term, synchronous staging) ----------------
#define FL_A    0
#define FL_W2   16384
#define FL_W1   49152
#define FL_B2   81920
#define FL_B1   82432
#define FL_SMEM_BYTES 82944

__global__ void __launch_bounds__(512, 1)
fused_linear_kernel(const unsigned char* __restrict__ w2img, const float* __restrict__ b2,
                    const unsigned char* __restrict__ w1img, const float* __restrict__ b1,
                    const float* __restrict__ b2next)
{
    extern __shared__ unsigned char base[];
    const uint32_t base32 = smem_u32(base);

    const int tid  = threadIdx.x;
    const int lane = tid & 31;
    const int wid  = tid >> 5;
    const int m0w  = (wid & 3) * 16;
    const int n0w  = (wid >> 2) * 32;
    const int r0   = blockIdx.x * 64;

    {
        const uint4* s2 = (const uint4*)w2img;
        const uint4* s1 = (const uint4*)w1img;
        uint4* d2 = (uint4*)(base + FL_W2);
        uint4* d1 = (uint4*)(base + FL_W1);
        for (int i = tid; i < 2048; i += 512) { d2[i] = s2[i]; d1[i] = s1[i]; }
        float* sb2 = (float*)(base + FL_B2);
        float* sb1 = (float*)(base + FL_B1);
        if (tid < 128) { sb2[tid] = b2[tid]; sb1[tid] = b1[tid]; }
    }

    {
        const int r  = tid >> 3;
        const int k0 = (tid & 7) * 16;
        const float4* xp = (const float4*)(g_agg + (r0 + r) * 128 + k0);
        float4 v0 = xp[0], v1 = xp[1], v2 = xp[2], v3 = xp[3];
        float vv[16];
        *(float4*)&vv[0]  = v0; *(float4*)&vv[4]  = v1;
        *(float4*)&vv[8]  = v2; *(float4*)&vv[12] = v3;
        #pragma unroll
        for (int g = 0; g < 2; g++) {
            uint4 hi;
            uint32_t* hp = (uint32_t*)&hi;
            #pragma unroll
            for (int j = 0; j < 4; j++)
                hp[j] = packbf2(vv[g*8 + 2*j], vv[g*8 + 2*j + 1]);
            *(uint4*)(base + FL_A + off2(r, k0 + g * 8)) = hi;
        }
    }
    __syncthreads();

    const int lr = lane & 15;
    const int lk = (lane >> 4) * 8;

    float acc[4][4];
    #pragma unroll
    for (int nj = 0; nj < 4; nj++)
        #pragma unroll
        for (int q = 0; q < 4; q++) acc[nj][q] = 0.0f;

    // GEMM A: agg @ W2
    #pragma unroll
    for (int ks = 0; ks < 8; ks++) {
        const int kb = ks * 16 + lk;
        uint32_t Ah[4];
        ldsm4(Ah, base32 + FL_A + off2(m0w + lr, kb));
        #pragma unroll
        for (int nt = 0; nt < 2; nt++) {
            uint32_t Bh[4];
            ldsm4(Bh, base32 + FL_W2 + off2(n0w + nt * 16 + lr, kb));
            #pragma unroll
            for (int h = 0; h < 2; h++)
                mma16816(acc[nt * 2 + h], Ah, Bh[h], Bh[2 + h]);
        }
    }
    __syncthreads();

    // epilogue A: h_new = h_old + silu(acc + b2); restage bf16
    {
        float* sb2 = (float*)(base + FL_B2);
        const int rbase = m0w + (lane >> 2);
        const int cbase = n0w + (lane & 3) * 2;
        #pragma unroll
        for (int nj = 0; nj < 4; nj++) {
            const int col = cbase + nj * 8;
            const float bb0 = sb2[col], bb1 = sb2[col + 1];
            #pragma unroll
            for (int half = 0; half < 2; half++) {
                const int rloc = rbase + half * 8;
                const int row  = r0 + rloc;
                float2* hptr = (float2*)(g_h + row * 128 + col);
                float2 hv = *hptr;
                const float v0 = hv.x + silu_f(acc[nj][half * 2]     + bb0);
                const float v1 = hv.y + silu_f(acc[nj][half * 2 + 1] + bb1);
                float2 nv; nv.x = v0; nv.y = v1;
                *hptr = nv;
                *(uint32_t*)(base + FL_A + off2(rloc, col)) = packbf2(v0, v1);
            }
        }
    }
    __syncthreads();

    #pragma unroll
    for (int nj = 0; nj < 4; nj++)
        #pragma unroll
        for (int q = 0; q < 4; q++) acc[nj][q] = 0.0f;

    // GEMM B: h_new @ W1
    #pragma unroll
    for (int ks = 0; ks < 8; ks++) {
        const int kb = ks * 16 + lk;
        uint32_t Ah[4];
        ldsm4(Ah, base32 + FL_A + off2(m0w + lr, kb));
        #pragma unroll
        for (int nt = 0; nt < 2; nt++) {
            uint32_t Bh[4];
            ldsm4(Bh, base32 + FL_W1 + off2(n0w + nt * 16 + lr, kb));
            #pragma unroll
            for (int h = 0; h < 2; h++)
                mma16816(acc[nt * 2 + h], Ah, Bh[h], Bh[2 + h]);
        }
    }

    // epilogue B: x1 = acc + b1; x1q = x1*b2next; zero agg rows
    {
        float* sb1 = (float*)(base + FL_B1);
        const int rbase = m0w + (lane >> 2);
        const int cbase = n0w + (lane & 3) * 2;
        #pragma unroll
        for (int nj = 0; nj < 4; nj++) {
            const int col = cbase + nj * 8;
            const float bb0 = sb1[col], bb1 = sb1[col + 1];
            const float q0 = b2next[col], q1 = b2next[col + 1];
            #pragma unroll
            for (int half = 0; half < 2; half++) {
                const int row = r0 + rbase + half * 8;
                const float v0 = acc[nj][half * 2]     + bb0;
                const float v1 = acc[nj][half * 2 + 1] + bb1;
                float2 v; v.x = v0; v.y = v1;
                *(float2*)(g_x1 + row * 128 + col) = v;
                float2 q; q.x = v0 * q0; q.y = v1 * q1;
                *(float2*)(g_x1q + row * 128 + col) = q;
            }
        }
    }
    {
        const int r  = r0 + (tid >> 3);
        const int k0 = (tid & 7) * 16;
        float4 zz; zz.x = zz.y = zz.z = zz.w = 0.0f;
        float4* ap = (float4*)(g_agg + r * 128 + k0);
        ap[0] = zz; ap[1] = zz; ap[2] = zz; ap[3] = zz;
    }
}

// ---------------- final: last linear + output head + per-graph sum ----------------
// block = one graph (128 rows). h_new = h_old + silu(agg@W2+b2) (not written back);
// t = silu(h_new@OW1 + ob1); out[g] = sum(t * ow2) + ATOMS*ob2.
#define FF_A     0          // 32768 (128 rows, off2)
#define FF_W2    32768      // 32768
#define FF_O1    65536      // 16384
#define FF_B2    81920      // 512
#define FF_OB1   82432      // 256
#define FF_OW2   82688      // 256
#define FF_SMEM_BYTES 82944

__global__ void __launch_bounds__(512, 1)
final_kernel(const unsigned char* __restrict__ w2img, const float* __restrict__ b2,
             const float* __restrict__ ob1, const float* __restrict__ ow2,
             const float* __restrict__ ob2, float* __restrict__ out)
{
    extern __shared__ unsigned char base[];
    const uint32_t base32 = smem_u32(base);
    __shared__ float red[16];

    const int tid  = threadIdx.x;
    const int lane = tid & 31;
    const int wid  = tid >> 5;
    const int m0w  = (wid & 7) * 16;       // 8 row-groups x 16 rows
    const int g0   = blockIdx.x * 128;     // graph base row

    // stage weights/biases
    {
        const uint4* s2 = (const uint4*)w2img;
        const uint4* so = (const uint4*)g_o1img;
        uint4* d2 = (uint4*)(base + FF_W2);
        uint4* d1 = (uint4*)(base + FF_O1);
        for (int i = tid; i < 2048; i += 512) d2[i] = s2[i];
        for (int i = tid; i < 1024; i += 512) d1[i] = so[i];
        float* sb2 = (float*)(base + FF_B2);
        if (tid < 128) sb2[tid] = b2[tid];
        float* so1 = (float*)(base + FF_OB1);
        float* so2 = (float*)(base + FF_OW2);
        if (tid < 64) { so1[tid] = ob1[tid]; so2[tid] = ow2[tid]; }
    }

    // stage agg rows (128) -> bf16
    #pragma unroll
    for (int rr = 0; rr < 2; rr++) {
        const int r  = rr * 64 + (tid >> 3);
        const int k0 = (tid & 7) * 16;
        const float4* xp = (const float4*)(g_agg + (g0 + r) * 128 + k0);
        float4 v0 = xp[0], v1 = xp[1], v2 = xp[2], v3 = xp[3];
        float vv[16];
        *(float4*)&vv[0]  = v0; *(float4*)&vv[4]  = v1;
        *(float4*)&vv[8]  = v2; *(float4*)&vv[12] = v3;
        #pragma unroll
        for (int g = 0; g < 2; g++) {
            uint4 hi;
            uint32_t* hp = (uint32_t*)&hi;
            #pragma unroll
            for (int j = 0; j < 4; j++)
                hp[j] = packbf2(vv[g*8 + 2*j], vv[g*8 + 2*j + 1]);
            *(uint4*)(base + FF_A + off2(r, k0 + g * 8)) = hi;
        }
    }
    __syncthreads();

    const int lr = lane & 15;
    const int lk = (lane >> 4) * 8;

    // GEMM A: agg @ W2  (warp: 16 rows x 64 cols)
    const int n0wA = (wid >> 3) * 64;
    float accA[8][4];
    #pragma unroll
    for (int nj = 0; nj < 8; nj++)
        #pragma unroll
        for (int q = 0; q < 4; q++) accA[nj][q] = 0.0f;

    #pragma unroll
    for (int ks = 0; ks < 8; ks++) {
        const int kb = ks * 16 + lk;
        uint32_t Ah[4];
        ldsm4(Ah, base32 + FF_A + off2(m0w + lr, kb));
        #pragma unroll
        for (int nt = 0; nt < 4; nt++) {
            uint32_t Bh[4];
            ldsm4(Bh, base32 + FF_W2 + off2(n0wA + nt * 16 + lr, kb));
            #pragma unroll
            for (int h = 0; h < 2; h++)
                mma16816(accA[nt * 2 + h], Ah, Bh[h], Bh[2 + h]);
        }
    }
    __syncthreads();

    // epilogue A: h_new = h_old + silu(acc + b2) -> restage bf16 (no h writeback)
    {
        float* sb2 = (float*)(base + FF_B2);
        const int rbase = m0w + (lane >> 2);
        const int cbase = n0wA + (lane & 3) * 2;
        #pragma unroll
        for (int nj = 0; nj < 8; nj++) {
            const int col = cbase + nj * 8;
            const float bb0 = sb2[col], bb1 = sb2[col + 1];
            #pragma unroll
            for (int half = 0; half < 2; half++) {
                const int rloc = rbase + half * 8;
                const float2 hv = *(const float2*)(g_h + (g0 + rloc) * 128 + col);
                const float v0 = hv.x + silu_f(accA[nj][half * 2]     + bb0);
                const float v1 = hv.y + silu_f(accA[nj][half * 2 + 1] + bb1);
                *(uint32_t*)(base + FF_A + off2(rloc, col)) = packbf2(v0, v1);
            }
        }
    }
    __syncthreads();

    // GEMM B: h_new @ OW1 (warp: 16 rows x 32 cols, N=64)
    const int n0wB = (wid >> 3) * 32;
    float accB[4][4];
    #pragma unroll
    for (int nj = 0; nj < 4; nj++)
        #pragma unroll
        for (int q = 0; q < 4; q++) accB[nj][q] = 0.0f;

    #pragma unroll
    for (int ks = 0; ks < 8; ks++) {
        const int kb = ks * 16 + lk;
        uint32_t Ah[4];
        ldsm4(Ah, base32 + FF_A + off2(m0w + lr, kb));
        #pragma unroll
        for (int nt = 0; nt < 2; nt++) {
            uint32_t Bh[4];
            ldsm4(Bh, base32 + FF_O1 + off2(n0wB + nt * 16 + lr, kb));
            #pragma unroll
            for (int h = 0; h < 2; h++)
                mma16816(accB[nt * 2 + h], Ah, Bh[h], Bh[2 + h]);
        }
    }

    // epilogue B: s = sum silu(acc + ob1) * ow2
    float s = 0.0f;
    {
        float* so1 = (float*)(base + FF_OB1);
        float* so2 = (float*)(base + FF_OW2);
        const int cbase = n0wB + (lane & 3) * 2;
        #pragma unroll
        for (int nj = 0; nj < 4; nj++) {
            const int col = cbase + nj * 8;
            const float bo0 = so1[col], bo1 = so1[col + 1];
            const float w0  = so2[col], w1  = so2[col + 1];
            #pragma unroll
            for (int half = 0; half < 2; half++) {
                s += silu_f(accB[nj][half * 2]     + bo0) * w0;
                s += silu_f(accB[nj][half * 2 + 1] + bo1) * w1;
            }
        }
    }
    #pragma unroll
    for (int o = 16; o >= 1; o >>= 1)
        s += __shfl_xor_sync(0xffffffffu, s, o);
    if (lane == 0) red[wid] = s;
    __syncthreads();
    if (wid == 0) {
        float v = (lane < 16) ? red[lane] : 0.0f;
        #pragma unroll
        for (int o = 8; o >= 1; o >>= 1)
            v += __shfl_down_sync(0xffffffffu, v, o);
        if (lane == 0) out[blockIdx.x] = v + (float)ATOMS * ob2[0];
    }
}

// ---------------- tensor-core filter kernel, 512 threads ----------------
#define SO_A1   0                 // 2 x 16384 (parity)
#define SO_A2   32768             // 32768
#define SO_B1   65536             // 16384
#define SO_B2   81920             // 32768
#define SO_AUX  114688            // 2 x 5120 (parity)
#define AUXB_X1P 0
#define AUXB_X1Q 2048
#define AUXB_CV  4096
#define AUXB_DST 4608
#define FILT_SMEM_BYTES (SO_AUX + 10240)

__device__ __forceinline__ void filt_prefetch(uint32_t base32, int tile, int par, int tid)
{
    if (tile >= NTILES) return;
    const size_t tb = (size_t)tile * 16384;
    for (int i = tid; i < 1024; i += 512)
        cp_async16(base32 + SO_A1 + par * 16384 + i * 16, g_rbf_hi + tb + i * 16);
    const uint32_t auxb = base32 + SO_AUX + par * 5120;
    if (tid < 128) {
        cp_async16(auxb + AUXB_X1P + tid * 16,
                   (const unsigned char*)g_x1  + (size_t)tile * 2048 + tid * 16);
        cp_async16(auxb + AUXB_X1Q + tid * 16,
                   (const unsigned char*)g_x1q + (size_t)tile * 2048 + tid * 16);
    } else if (tid < 160) {
        const int j = tid - 128;
        cp_async16(auxb + AUXB_CV + j * 16,
                   (const unsigned char*)g_cval + (size_t)tile * 512 + j * 16);
    } else if (tid < 192) {
        const int j = tid - 160;
        cp_async16(auxb + AUXB_DST + j * 16,
                   (const unsigned char*)g_idx + (size_t)tile * 512 + j * 16);
    }
}

__global__ void __launch_bounds__(512, 1)
filter_mma_kernel(const unsigned char* __restrict__ w1hi,
                  const unsigned char* __restrict__ w2hi)
{
    extern __shared__ unsigned char base[];
    const uint32_t base32 = smem_u32(base);

    const int tid  = threadIdx.x;
    const int lane = tid & 31;
    const int wid  = tid >> 5;
    const int wm   = wid & 3;          // warp m-tile: 32 edges
    const int wn   = wid >> 2;         // warp n-tile: 32 channels
    const int m0w  = wm * 32;
    const int n0w  = wn * 32;

    // resident weight copies
    {
        const uint4* s1h = (const uint4*)w1hi;
        const uint4* s2h = (const uint4*)w2hi;
        uint4* d1h = (uint4*)(base + SO_B1);
        uint4* d2h = (uint4*)(base + SO_B2);
        for (int i = tid; i < 1024; i += 512) d1h[i] = s1h[i];
        for (int i = tid; i < 2048; i += 512) d2h[i] = s2h[i];
    }

    filt_prefetch(base32, blockIdx.x, 0, tid);
    CP_COMMIT();

    const int lr = lane & 15;
    const int lk = (lane >> 4) * 8;

    __syncthreads();    // weights visible

    // B1 fragments register-resident (tile-invariant)
    uint32_t B1r[4][2][4];
    #pragma unroll
    for (int ks = 0; ks < 4; ks++) {
        const int kb = ks * 16 + lk;
        #pragma unroll
        for (int nt = 0; nt < 2; nt++)
            ldsm4(B1r[ks][nt], base32 + SO_B1 + off1(n0w + nt * 16 + lr, kb));
    }

    int par = 0;
    for (int tile = blockIdx.x; tile < NTILES; tile += gridDim.x, par ^= 1) {
        unsigned char* aux = base + SO_AUX + par * 5120;
        float* sx1p = (float*)(aux + AUXB_X1P);
        float* sx1q = (float*)(aux + AUXB_X1Q);
        float* scv  = (float*)(aux + AUXB_CV);
        int*   sdst = (int*)  (aux + AUXB_DST);

        CP_WAIT0();
        __syncthreads();

        filt_prefetch(base32, tile + gridDim.x, par ^ 1, tid);
        CP_COMMIT();

        float acc[2][4][4];
        #pragma unroll
        for (int mi = 0; mi < 2; mi++)
            #pragma unroll
            for (int nj = 0; nj < 4; nj++)
                #pragma unroll
                for (int q = 0; q < 4; q++) acc[mi][nj][q] = 0.0f;

        // ---- GEMM1: K=64 (bias folded), B from registers ----
        const uint32_t a1b = base32 + SO_A1 + par * 16384;
        #pragma unroll
        for (int ks = 0; ks < 4; ks++) {
            const int kb = ks * 16 + lk;
            uint32_t Ah[2][4];
            #pragma unroll
            for (int mi = 0; mi < 2; mi++)
                ldsm4(Ah[mi], a1b + off1(m0w + mi * 16 + lr, kb));
            #pragma unroll
            for (int nt = 0; nt < 2; nt++)
                #pragma unroll
                for (int h = 0; h < 2; h++) {
                    const int nj = nt * 2 + h;
                    #pragma unroll
                    for (int mi = 0; mi < 2; mi++)
                        mma16816(acc[mi][nj], Ah[mi], B1r[ks][nt][h], B1r[ks][nt][2 + h]);
                }
        }

        // ---- epilogue1: silu -> bf16 -> A2 ----
        {
            unsigned char* a2h = base + SO_A2;
            const int rbase = m0w + (lane >> 2);
            const int cbase = n0w + (lane & 3) * 2;
            #pragma unroll
            for (int mi = 0; mi < 2; mi++)
                #pragma unroll
                for (int nj = 0; nj < 4; nj++) {
                    const int col = cbase + nj * 8;
                    #pragma unroll
                    for (int half = 0; half < 2; half++) {
                        const int row = rbase + mi * 16 + half * 8;
                        const float s0 = silu_f(acc[mi][nj][half * 2]);
                        const float s1 = silu_f(acc[mi][nj][half * 2 + 1]);
                        *(uint32_t*)(a2h + off2(row, col)) = packbf2(s0, s1);
                    }
                }
        }
        asm volatile("bar.sync %0, %1;" :: "r"(1 + wm), "r"(128) : "memory");

        #pragma unroll
        for (int mi = 0; mi < 2; mi++)
            #pragma unroll
            for (int nj = 0; nj < 4; nj++)
                #pragma unroll
                for (int q = 0; q < 4; q++) acc[mi][nj][q] = 0.0f;

        // ---- GEMM2: K=128 ----
        #pragma unroll
        for (int ks = 0; ks < 8; ks++) {
            const int kb = ks * 16 + lk;
            uint32_t Ah[2][4];
            #pragma unroll
            for (int mi = 0; mi < 2; mi++)
                ldsm4(Ah[mi], base32 + SO_A2 + off2(m0w + mi * 16 + lr, kb));
            #pragma unroll
            for (int nt = 0; nt < 2; nt++) {
                uint32_t Bh[4];
                ldsm4(Bh, base32 + SO_B2 + off2(n0w + nt * 16 + lr, kb));
                #pragma unroll
                for (int h = 0; h < 2; h++) {
                    const int nj = nt * 2 + h;
                    #pragma unroll
                    for (int mi = 0; mi < 2; mi++)
                        mma16816(acc[mi][nj], Ah[mi], Bh[h], Bh[2 + h]);
                }
            }
        }

        // ---- epilogue2: permuted channels -> red.v4 ----
        {
            const int q4 = (lane & 3) << 2;
            const int rbase = m0w + (lane >> 2);
            const int j4 = m0w >> 5;
            const float* pv = &sx1p[j4 * 128];
            const float* qv = &sx1q[j4 * 128];
            #pragma unroll
            for (int mi = 0; mi < 2; mi++)
                #pragma unroll
                for (int half = 0; half < 2; half++) {
                    const int row = rbase + mi * 16 + half * 8;
                    const float cv = scv[row];
                    const int   dst = sdst[row];
                    float* aggp = &g_agg[dst * 128];
                    #pragma unroll
                    for (int pj = 0; pj < 2; pj++) {
                        const int pb = n0w + (pj << 4) + q4;
                        const float4 pvv = *(const float4*)&pv[pb];
                        const float4 qvv = *(const float4*)&qv[pb];
                        const float m0 = cv * fmaf(acc[mi][2*pj    ][half * 2],     pvv.x, qvv.x);
                        const float m1 = cv * fmaf(acc[mi][2*pj    ][half * 2 + 1], pvv.y, qvv.y);
                        const float m2 = cv * fmaf(acc[mi][2*pj + 1][half * 2],     pvv.z, qvv.z);
                        const float m3 = cv * fmaf(acc[mi][2*pj + 1][half * 2 + 1], pvv.w, qvv.w);
                        red_add_v4(aggp + pb, m0, m1, m2, m3);
                    }
                }
        }
    }
}

// ---------------- launch ----------------
extern "C" void kernel_launch(void* const* d_in, const int* in_sizes, int n_in,
                              void* d_out, int out_size)
{
    const float* pos   = (const float*)d_in[0];
    const int*   z     = (const int*)  d_in[1];
    const int*   batch = (const int*)  d_in[2];
    const float* emb   = (const float*)d_in[3];
    const float* mw1   = (const float*)d_in[4];
    const float* mb1   = (const float*)d_in[5];
    const float* mw2   = (const float*)d_in[6];
    const float* mb2   = (const float*)d_in[7];
    const float* l1w   = (const float*)d_in[8];
    const float* l1b   = (const float*)d_in[9];
    const float* l2w   = (const float*)d_in[10];
    const float* l2b   = (const float*)d_in[11];
    const float* ow1   = (const float*)d_in[12];
    const float* ob1   = (const float*)d_in[13];
    const float* ow2   = (const float*)d_in[14];
    const float* ob2   = (const float*)d_in[15];
    float* out = (float*)d_out;

    float *hp, *x1p, *aggp;
    cudaGetSymbolAddress((void**)&hp,   g_h);
    cudaGetSymbolAddress((void**)&x1p,  g_x1);
    cudaGetSymbolAddress((void**)&aggp, g_agg);
    unsigned char *w1h, *w2h, *l1i, *l2i;
    cudaGetSymbolAddress((void**)&w1h, g_w1_hi);
    cudaGetSymbolAddress((void**)&w2h, g_w2_hi);
    cudaGetSymbolAddress((void**)&l1i, g_l1img);
    cudaGetSymbolAddress((void**)&l2i, g_l2img);

    cudaFuncSetAttribute(filter_mma_kernel, cudaFuncAttributeMaxDynamicSharedMemorySize,
                         FILT_SMEM_BYTES);
    cudaFuncSetAttribute(linear_mma_kernel, cudaFuncAttributeMaxDynamicSharedMemorySize,
                         LIN_SMEM_BYTES);
    cudaFuncSetAttribute(fused_linear_kernel, cudaFuncAttributeMaxDynamicSharedMemorySize,
                         FL_SMEM_BYTES);
    cudaFuncSetAttribute(final_kernel, cudaFuncAttributeMaxDynamicSharedMemorySize,
                         FF_SMEM_BYTES);

    build_graph_kernel<<<NTOT / 4, 128>>>(pos, batch);
    rbf_prep_kernel<<<EDGES / 256, 256>>>();
    prep_all_kernel<<<(PREP_TOTAL + 255) / 256, 256>>>(mw1, mb1, mw2, l1w, l2w, ow1, z, emb);

    linear_mma_kernel<<<NTOT / 64, 512, LIN_SMEM_BYTES>>>(
        hp, l1i, l1b, mb2, x1p, 0);

    for (int l = 0; l < LAYERS; l++) {
        filter_mma_kernel<<<148, 512, FILT_SMEM_BYTES>>>(
            w1h + l * 16384, w2h + l * 32768);
        if (l < LAYERS - 1) {
            fused_linear_kernel<<<NTOT / 64, 512, FL_SMEM_BYTES>>>(
                l2i + l * 32768, l2b + l * HID,
                l1i + (l + 1) * 32768, l1b + (l + 1) * FIL,
                mb2 + (l + 1) * FIL);
        }
    }

    final_kernel<<<NUM_G, 512, FF_SMEM_BYTES>>>(
        l2i + (LAYERS - 1) * 32768, l2b + (LAYERS - 1) * HID,
        ob1, ow2, ob2, out);
}